// round 1
// baseline (speedup 1.0000x reference)
#include <cuda_runtime.h>
#include <math.h>

// Problem constants (fixed by setup_inputs): B=2, N=6890, NF=2000
#define B_    2
#define NMAX  7168
#define NFMAX 2048

// -------- device scratch (no allocations allowed) --------
// points, SoA: [cloud (0=v1,1=v2)][component][b*N+n]
__device__ float g_pts[2][3][B_ * NMAX];
// gathered triangle vertices, SoA: [src (0=t1 from v1, 1=t2 from v2)][9 comps][b*NF+f]
__device__ float g_tri[2][9][B_ * NFMAX];
// winding numbers: [dir (0: v1 vs t2, 1: v2 vs t1)][b*N+n]
__device__ float g_wind[2][B_ * NMAX];
// squared min distances: [dir (0: row_min v1->v2, 1: col_min v2->v1)][b*N+n]
__device__ float g_minsq[2][B_ * NMAX];

// ---------------------------------------------------------
// fast atan2: minimax odd polynomial on [0,1], abs err ~6e-7
// ---------------------------------------------------------
__device__ __forceinline__ float fast_atan2f(float y, float x) {
    float ax = fabsf(x), ay = fabsf(y);
    float mx = fmaxf(ax, ay);
    float mn = fminf(ax, ay);
    if (mx == 0.0f) return 0.0f;           // atan2(0,0) = 0
    float t = __fdividef(mn, mx);          // in [0,1]
    float s = t * t;
    float p = fmaf(s, -0.01172120f, 0.05265332f);
    p = fmaf(s, p, -0.11643287f);
    p = fmaf(s, p,  0.19354346f);
    p = fmaf(s, p, -0.33262347f);
    p = fmaf(s, p,  0.99997726f);
    float r = p * t;
    if (ay > ax)  r = 1.57079632679f - r;
    if (x < 0.0f) r = 3.14159265359f - r;
    return (y < 0.0f) ? -r : r;
}

// ---------------------------------------------------------
// gather: build SoA point arrays and gathered triangle soup
// ---------------------------------------------------------
__global__ void gather_kernel(const float* __restrict__ v1,
                              const float* __restrict__ v2,
                              const int*   __restrict__ faces,
                              int N, int NF) {
    int stride = gridDim.x * blockDim.x;
    int t0 = blockIdx.x * blockDim.x + threadIdx.x;

    int PT = B_ * N;
    for (int i = t0; i < PT; i += stride) {
        #pragma unroll
        for (int c = 0; c < 3; c++) {
            g_pts[0][c][i] = v1[i * 3 + c];
            g_pts[1][c][i] = v2[i * 3 + c];
        }
    }

    int FT = B_ * NF;
    for (int i = t0; i < FT; i += stride) {
        int b = i / NF;
        int f = i - b * NF;
        int i0 = faces[f * 3 + 0];
        int i1 = faces[f * 3 + 1];
        int i2 = faces[f * 3 + 2];
        int base = b * N * 3;
        #pragma unroll
        for (int c = 0; c < 3; c++) {
            g_tri[0][0 + c][i] = v1[base + i0 * 3 + c];
            g_tri[0][3 + c][i] = v1[base + i1 * 3 + c];
            g_tri[0][6 + c][i] = v1[base + i2 * 3 + c];
            g_tri[1][0 + c][i] = v2[base + i0 * 3 + c];
            g_tri[1][3 + c][i] = v2[base + i1 * 3 + c];
            g_tri[1][6 + c][i] = v2[base + i2 * 3 + c];
        }
    }
}

// ---------------------------------------------------------
// winding numbers: one warp per point, lanes stride triangles
// dir 0: points=v1 vs tris=t2 (src 1); dir 1: points=v2 vs t1 (src 0)
// ---------------------------------------------------------
__global__ void __launch_bounds__(256)
winding_kernel(int N, int NF) {
    int gt = blockIdx.x * 256 + threadIdx.x;
    int w = gt >> 5;
    int lane = gt & 31;
    int total = 2 * B_ * N;
    if (w >= total) return;

    int dir = (w >= B_ * N) ? 1 : 0;
    int r = w - dir * (B_ * N);
    int b = r / N;
    int src = 1 - dir;
    int base = b * NF;

    float px = g_pts[dir][0][r];
    float py = g_pts[dir][1][r];
    float pz = g_pts[dir][2][r];

    const float* __restrict__ T0 = g_tri[src][0];
    const float* __restrict__ T1 = g_tri[src][1];
    const float* __restrict__ T2 = g_tri[src][2];
    const float* __restrict__ T3 = g_tri[src][3];
    const float* __restrict__ T4 = g_tri[src][4];
    const float* __restrict__ T5 = g_tri[src][5];
    const float* __restrict__ T6 = g_tri[src][6];
    const float* __restrict__ T7 = g_tri[src][7];
    const float* __restrict__ T8 = g_tri[src][8];

    float acc = 0.0f;
    for (int f = lane; f < NF; f += 32) {
        int e = base + f;
        float ax = T0[e] - px, ay = T1[e] - py, az = T2[e] - pz;
        float bx = T3[e] - px, by = T4[e] - py, bz = T5[e] - pz;
        float cx = T6[e] - px, cy = T7[e] - py, cz = T8[e] - pz;

        float la = sqrtf(fmaf(ax, ax, fmaf(ay, ay, az * az)));
        float lb = sqrtf(fmaf(bx, bx, fmaf(by, by, bz * bz)));
        float lc = sqrtf(fmaf(cx, cx, fmaf(cy, cy, cz * cz)));

        float crx = fmaf(by, cz, -bz * cy);
        float cry = fmaf(bz, cx, -bx * cz);
        float crz = fmaf(bx, cy, -by * cx);
        float det = fmaf(ax, crx, fmaf(ay, cry, az * crz));

        float dab = fmaf(ax, bx, fmaf(ay, by, az * bz));
        float dbc = fmaf(bx, cx, fmaf(by, cy, bz * cz));
        float dca = fmaf(cx, ax, fmaf(cy, ay, cz * az));

        float denom = fmaf(la * lb, lc, fmaf(dab, lc, fmaf(dbc, la, dca * lb)));
        acc += fast_atan2f(det, denom);
    }
    #pragma unroll
    for (int o = 16; o; o >>= 1)
        acc += __shfl_xor_sync(0xffffffffu, acc, o);
    if (lane == 0)
        g_wind[dir][r] = acc * 0.15915494309189535f;   // sum(2*atan2)/(4*pi) = sum/(2*pi)
}

// ---------------------------------------------------------
// squared min distances: one warp per point vs the other cloud
// ---------------------------------------------------------
__global__ void __launch_bounds__(256)
minsq_kernel(int N) {
    int gt = blockIdx.x * 256 + threadIdx.x;
    int w = gt >> 5;
    int lane = gt & 31;
    int total = 2 * B_ * N;
    if (w >= total) return;

    int dir = (w >= B_ * N) ? 1 : 0;
    int r = w - dir * (B_ * N);
    int b = r / N;
    int oth = 1 - dir;

    float px = g_pts[dir][0][r];
    float py = g_pts[dir][1][r];
    float pz = g_pts[dir][2][r];

    const float* __restrict__ ox = g_pts[oth][0] + b * N;
    const float* __restrict__ oy = g_pts[oth][1] + b * N;
    const float* __restrict__ oz = g_pts[oth][2] + b * N;

    float best = 3.4e38f;
    int m = lane;
    #pragma unroll 4
    for (; m < N; m += 32) {
        float dx = ox[m] - px;
        float dy = oy[m] - py;
        float dz = oz[m] - pz;
        best = fminf(best, fmaf(dx, dx, fmaf(dy, dy, dz * dz)));
    }
    #pragma unroll
    for (int o = 16; o; o >>= 1)
        best = fminf(best, __shfl_xor_sync(0xffffffffu, best, o));
    if (lane == 0)
        g_minsq[dir][r] = best;
}

// ---------------------------------------------------------
// finalize: masked stats + global min, single block
// out layout: [5][B] row-major (stack axis=0)
// ---------------------------------------------------------
__global__ void finalize_kernel(float* __restrict__ out, int N) {
    __shared__ float sh[256 * 7];
    int tid = threadIdx.x;
    for (int b = 0; b < B_; b++) {
        float mn = 3.4e38f;
        float mx1 = -1e30f, s1 = 0.0f, c1 = 0.0f;
        float mx2 = -1e30f, s2 = 0.0f, c2 = 0.0f;
        for (int n = tid; n < N; n += 256) {
            int i = b * N + n;
            float rm = sqrtf(g_minsq[0][i]);
            mn = fminf(mn, rm);
            if (g_wind[0][i] >= 0.99f) { mx1 = fmaxf(mx1, rm); s1 += rm; c1 += 1.0f; }
            float cm = sqrtf(g_minsq[1][i]);
            if (g_wind[1][i] >= 0.99f) { mx2 = fmaxf(mx2, cm); s2 += cm; c2 += 1.0f; }
        }
        sh[tid]            = mn;
        sh[256  + tid]     = mx1;
        sh[512  + tid]     = s1;
        sh[768  + tid]     = c1;
        sh[1024 + tid]     = mx2;
        sh[1280 + tid]     = s2;
        sh[1536 + tid]     = c2;
        __syncthreads();
        if (tid == 0) {
            for (int t = 1; t < 256; t++) {
                mn  = fminf(mn,  sh[t]);
                mx1 = fmaxf(mx1, sh[256 + t]);
                s1 += sh[512 + t];
                c1 += sh[768 + t];
                mx2 = fmaxf(mx2, sh[1024 + t]);
                s2 += sh[1280 + t];
                c2 += sh[1536 + t];
            }
            out[0 * B_ + b] = mn;
            out[1 * B_ + b] = (c1 > 0.0f) ? mx1 : 0.0f;
            out[2 * B_ + b] = (c1 > 0.0f) ? s1 / fmaxf(c1, 1.0f) : 0.0f;
            out[3 * B_ + b] = (c2 > 0.0f) ? mx2 : 0.0f;
            out[4 * B_ + b] = (c2 > 0.0f) ? s2 / fmaxf(c2, 1.0f) : 0.0f;
        }
        __syncthreads();
    }
}

// ---------------------------------------------------------
extern "C" void kernel_launch(void* const* d_in, const int* in_sizes, int n_in,
                              void* d_out, int out_size) {
    const float* v1 = (const float*)d_in[0];
    const float* v2 = (const float*)d_in[1];
    const int* faces = (const int*)d_in[2];
    float* out = (float*)d_out;

    int N = in_sizes[0] / (3 * B_);   // 6890
    int NF = in_sizes[2] / 3;         // 2000

    int gwork = B_ * N;
    if (B_ * NF > gwork) gwork = B_ * NF;
    gather_kernel<<<(gwork + 255) / 256, 256>>>(v1, v2, faces, N, NF);

    int warps = 2 * B_ * N;
    int blocks = (warps * 32 + 255) / 256;
    winding_kernel<<<blocks, 256>>>(N, NF);
    minsq_kernel<<<blocks, 256>>>(N);
    finalize_kernel<<<1, 256>>>(out, N);
}